// round 1
// baseline (speedup 1.0000x reference)
#include <cuda_runtime.h>
#include <math.h>

#define NN   20000
#define FF   64
#define EE   320000
#define GG   20
#define NGG  1000
#define NELS 10
#define NBB  8
#define RMAXF 5.0f
#define HML  16

// output layout (float32, 20160 elems):
#define OUT_TE      0        // [20]  total_energy
#define OUT_NE      20       // [20000] node_energy
#define OUT_CONTRIB 20020    // [20,3] contributions
#define OUT_POL     20080    // [20,3] pol
#define OUT_TC      20140    // [20]  total_charge
#define OUT_TOTAL   20160

// ---------------- device scratch (no allocation allowed) ----------------
__device__ float g_sc[NN * FF];     // current node scalars
__device__ float g_agg[NN * FF];    // per-layer aggregation (s=0 only!)
__device__ float g_ef[EE * NBB];    // compacted active-edge radial features
__device__ int   g_asnd[EE];
__device__ int   g_arcv[EE];
__device__ float g_cd[NN];          // charge density
__device__ int   g_count;           // active edge count

// ---------------- K0: zero everything that accumulates ----------------
__global__ void k_zero(float* __restrict__ out) {
    int i = blockIdx.x * blockDim.x + threadIdx.x;
    if (i < NN * FF) g_agg[i] = 0.0f;
    if (i < OUT_TOTAL) out[i] = 0.0f;
    if (i == 0) g_count = 0;
}

// ---------------- K1: node init (embed, E0, FQ, pol node part) ----------------
__global__ void k_node_init(const float* __restrict__ attrs,
                            const float* __restrict__ pos,
                            const int*   __restrict__ batch,
                            const float* __restrict__ ae,
                            const float* __restrict__ embw,
                            const float* __restrict__ fc,
                            float* __restrict__ out) {
    int n = blockIdx.x;
    int f = threadIdx.x;
    __shared__ float at[NELS];
    __shared__ float fq_s;
    if (f < NELS) at[f] = attrs[n * NELS + f];
    __syncthreads();
    float s = 0.0f;
#pragma unroll
    for (int k = 0; k < NELS; k++) s = fmaf(at[k], embw[k * FF + f], s);
    g_sc[n * FF + f] = s;
    if (f == 0) {
        float fq = 0.0f, ne0 = 0.0f;
#pragma unroll
        for (int k = 0; k < NELS; k++) { fq = fmaf(at[k], fc[k], fq); ne0 = fmaf(at[k], ae[k], ne0); }
        g_cd[n] = fq;
        out[OUT_NE + n] = ne0;
        int g = batch[n];
        atomicAdd(&out[OUT_CONTRIB + g * 3 + 0], ne0);
        fq_s = fq;
    }
    __syncthreads();
    if (f < 3) {
        int g = batch[n];
        atomicAdd(&out[OUT_POL + g * 3 + f], fq_s * pos[n * 3 + f]);
    }
}

// ---------------- K2: edge geometry + radial basis + flux/pol + compaction ----------------
__global__ void k_edge_geom(const float* __restrict__ pos,
                            const int*   __restrict__ ei,
                            const int*   __restrict__ batch,
                            const float* __restrict__ fw,   // flux_w [2,8]
                            float* __restrict__ out) {
    int e = blockIdx.x * blockDim.x + threadIdx.x;
    if (e >= EE) return;
    int snd = ei[e], rcv = ei[EE + e];
    float dx = pos[rcv * 3 + 0] - pos[snd * 3 + 0];
    float dy = pos[rcv * 3 + 1] - pos[snd * 3 + 1];
    float dz = pos[rcv * 3 + 2] - pos[snd * 3 + 2];
    float r = sqrtf(fmaf(dx, dx, fmaf(dy, dy, dz * dz)) + 1e-12f);
    if (r >= RMAXF) return;     // ef==0 -> contributes nothing anywhere
    float x = r * (1.0f / RMAXF);
    float x2 = x * x;
    float x5 = x2 * x2 * x;
    float u = 1.0f + x5 * (-21.0f + x * (35.0f - 15.0f * x));
    float pref = 0.6324555320336759f * u / r;     // sqrt(2/5) * u / r
    float s1, c1;
    sincosf(r * 0.6283185307179586f, &s1, &c1);   // pi/5 * r
    float sn = s1, cn = c1;
    float ef[NBB];
    float flux = 0.0f;
#pragma unroll
    for (int i = 0; i < NBB; i++) {
        float v = pref * sn;
        ef[i] = v;
        flux = fmaf(v, fw[i] + fw[NBB + i], flux);  // both layers' flux weights
        float sn2 = sn * c1 + cn * s1;
        cn = cn * c1 - sn * s1;
        sn = sn2;
    }
    int slot = atomicAdd(&g_count, 1);
#pragma unroll
    for (int i = 0; i < NBB; i++) g_ef[slot * NBB + i] = ef[i];
    g_asnd[slot] = snd;
    g_arcv[slot] = rcv;
    int g = batch[rcv];
    atomicAdd(&out[OUT_POL + g * 3 + 0], flux * dx);
    atomicAdd(&out[OUT_POL + g * 3 + 1], flux * dy);
    atomicAdd(&out[OUT_POL + g * 3 + 2], flux * dz);
}

// ---------------- K4: per-edge radial MLP + message scatter (s=0 only) ----------------
__global__ void __launch_bounds__(256, 2)
k_edge_mlp(const float* __restrict__ W1,   // [8,64]
           const float* __restrict__ B1,   // [64]
           const float* __restrict__ W2) { // [64,64]
    int f = threadIdx.x & 63;
    int grp = threadIdx.x >> 6;
    float w1r[NBB];
#pragma unroll
    for (int i = 0; i < NBB; i++) w1r[i] = W1[i * FF + f];
    float b1r = B1[f];
    float w2c[FF];
#pragma unroll
    for (int j = 0; j < FF; j++) w2c[j] = W2[j * FF + f];

    __shared__ float4 hsm4[4][16];

    int count = g_count;
    int stride = gridDim.x * 4;
    int trips = (count + stride - 1) / stride;
    for (int t = 0; t < trips; t++) {
        int slot = (t * gridDim.x + blockIdx.x) * 4 + grp;
        bool valid = slot < count;
        float h = 0.0f;
        if (valid) {
            const float* ef = &g_ef[slot * NBB];
            float acc = b1r;
#pragma unroll
            for (int i = 0; i < NBB; i++) acc = fmaf(__ldg(ef + i), w1r[i], acc);
            h = acc / (1.0f + __expf(-acc));     // silu
        }
        ((float*)&hsm4[grp][0])[f] = h;
        __syncthreads();
        float R = 0.0f;
#pragma unroll
        for (int j4 = 0; j4 < 16; j4++) {
            float4 h4 = hsm4[grp][j4];
            R = fmaf(h4.x, w2c[j4 * 4 + 0], R);
            R = fmaf(h4.y, w2c[j4 * 4 + 1], R);
            R = fmaf(h4.z, w2c[j4 * 4 + 2], R);
            R = fmaf(h4.w, w2c[j4 * 4 + 3], R);
        }
        if (valid) {
            int snd = g_asnd[slot];
            int rcv = g_arcv[slot];
            float msg = R * __ldg(&g_sc[snd * FF + f]);
            atomicAdd(&g_agg[rcv * FF + f], msg);
        }
        __syncthreads();
    }
}

// ---------------- K5: node update (product+skip, readout, charge) ----------------
__global__ void k_node_update(const float* __restrict__ attrs,
                              const int*   __restrict__ batch,
                              const float* __restrict__ PW,    // prod_w[l]  [10,64]
                              const float* __restrict__ CW,    // charge_w[l][64]
                              const float* __restrict__ ROW,   // readout_w[l][64] (l==0)
                              const float* __restrict__ RW1,   // ro2_w1 [64,16]
                              const float* __restrict__ RB1,   // ro2_b1 [16]
                              const float* __restrict__ RW2,   // ro2_w2 [16]
                              float* __restrict__ out,
                              int last, int cidx) {
    int n = blockIdx.x;
    int f = threadIdx.x;
    __shared__ float at[NELS];
    __shared__ float scsm[FF];
    __shared__ float red[FF];
    __shared__ float res_c, res_e;
    if (f < NELS) at[f] = attrs[n * NELS + f];
    __syncthreads();
    float a = g_agg[n * FF + f] * 0.0625f;   // / AVG_NEIGH
    g_agg[n * FF + f] = 0.0f;                // pre-zero for next layer
    float pw = 0.0f;
#pragma unroll
    for (int k = 0; k < NELS; k++) pw = fmaf(at[k], PW[k * FF + f], pw);
    float sco = g_sc[n * FF + f];
    float sc = fmaf(a, a, a) + sco * pw;
    g_sc[n * FF + f] = sc;
    scsm[f] = sc;

    // --- reduce charge contribution ---
    red[f] = sc * CW[f];
    __syncthreads();
    if (f < 32) {
        float v = red[f] + red[f + 32];
        v += __shfl_down_sync(0xffffffffu, v, 16);
        v += __shfl_down_sync(0xffffffffu, v, 8);
        v += __shfl_down_sync(0xffffffffu, v, 4);
        v += __shfl_down_sync(0xffffffffu, v, 2);
        v += __shfl_down_sync(0xffffffffu, v, 1);
        if (f == 0) res_c = v;
    }
    __syncthreads();

    // --- node energy ---
    if (!last) {
        red[f] = sc * ROW[f];
        __syncthreads();
        if (f < 32) {
            float v = red[f] + red[f + 32];
            v += __shfl_down_sync(0xffffffffu, v, 16);
            v += __shfl_down_sync(0xffffffffu, v, 8);
            v += __shfl_down_sync(0xffffffffu, v, 4);
            v += __shfl_down_sync(0xffffffffu, v, 2);
            v += __shfl_down_sync(0xffffffffu, v, 1);
            if (f == 0) res_e = v;
        }
        __syncthreads();
    } else {
        if (f < HML) {
            float acc = RB1[f];
#pragma unroll
            for (int j = 0; j < FF; j++) acc = fmaf(scsm[j], RW1[j * HML + f], acc);
            float hv = acc / (1.0f + __expf(-acc));
            red[f] = hv * RW2[f];
        }
        __syncthreads();
        if (f == 0) {
            float v = 0.0f;
#pragma unroll
            for (int m = 0; m < HML; m++) v += red[m];
            res_e = v;
        }
        __syncthreads();
    }

    if (f == 0) {
        g_cd[n] += res_c;
        out[OUT_NE + n] += res_e;
        int g = batch[n];
        atomicAdd(&out[OUT_CONTRIB + g * 3 + cidx], res_e);
    }
}

// ---------------- K6: screened Coulomb per graph ----------------
__global__ void k_coulomb(const float* __restrict__ pos, float* __restrict__ out) {
    int g = blockIdx.x >> 3;
    int part = blockIdx.x & 7;
    __shared__ float qs[NGG], px[NGG], py[NGG], pz[NGG];
    int base = g * NGG;
    for (int j = threadIdx.x; j < NGG; j += 128) {
        qs[j] = g_cd[base + j];
        px[j] = pos[(base + j) * 3 + 0];
        py[j] = pos[(base + j) * 3 + 1];
        pz[j] = pos[(base + j) * 3 + 2];
    }
    __syncthreads();
    int il = part * 125 + threadIdx.x;
    float e = 0.0f;
    if (threadIdx.x < 125) {
        float xi = px[il], yi = py[il], zi = pz[il], qi = qs[il];
        float acc = 0.0f;
        for (int j = 0; j < NGG; j++) {
            float dx = xi - px[j], dy = yi - py[j], dz = zi - pz[j];
            float r = sqrtf(fmaf(dx, dx, fmaf(dy, dy, dz * dz)) + 1e-12f);
            float kern = erff(0.5f * r) * __fdividef(1.0f, r);
            acc += (j != il) ? qs[j] * kern : 0.0f;
        }
        e = 0.5f * qi * acc;
    }
    // block reduce (4 warps)
    __shared__ float wred[4];
    float v = e;
    v += __shfl_down_sync(0xffffffffu, v, 16);
    v += __shfl_down_sync(0xffffffffu, v, 8);
    v += __shfl_down_sync(0xffffffffu, v, 4);
    v += __shfl_down_sync(0xffffffffu, v, 2);
    v += __shfl_down_sync(0xffffffffu, v, 1);
    if ((threadIdx.x & 31) == 0) wred[threadIdx.x >> 5] = v;
    __syncthreads();
    if (threadIdx.x == 0) {
        float s = wred[0] + wred[1] + wred[2] + wred[3];
        atomicAdd(&out[OUT_TE + g], s);
    }
}

// ---------------- K7: total charge ----------------
__global__ void k_total_charge(const int* __restrict__ batch, float* __restrict__ out) {
    int n = blockIdx.x * blockDim.x + threadIdx.x;
    if (n < NN) atomicAdd(&out[OUT_TC + batch[n]], g_cd[n]);
}

// ---------------- K8: finalize total energy ----------------
__global__ void k_finalize(float* __restrict__ out) {
    int g = threadIdx.x;
    if (g < GG) {
        out[OUT_TE + g] += out[OUT_CONTRIB + g * 3 + 0]
                         + out[OUT_CONTRIB + g * 3 + 1]
                         + out[OUT_CONTRIB + g * 3 + 2];
    }
}

// ---------------- launch ----------------
extern "C" void kernel_launch(void* const* d_in, const int* in_sizes, int n_in,
                              void* d_out, int out_size) {
    const float* node_attrs = (const float*)d_in[0];   // [N,10]
    const float* positions  = (const float*)d_in[1];   // [N,3]
    const int*   edge_index = (const int*)d_in[2];     // [2,E]
    const int*   batch      = (const int*)d_in[3];     // [N]
    // num_graphs may or may not appear as d_in[4]; detect by size of the
    // next array (atomic_energies has NELS=10 elements).
    int p = (in_sizes[4] == NELS) ? 4 : 5;
    const float* atomic_energies = (const float*)d_in[p + 0];   // [10]
    const float* embed_w         = (const float*)d_in[p + 1];   // [10,64]
    const float* radial_w1       = (const float*)d_in[p + 2];   // [2,8,64]
    const float* radial_b1       = (const float*)d_in[p + 3];   // [2,64]
    const float* radial_w2       = (const float*)d_in[p + 4];   // [2,64,64]
    const float* prod_w          = (const float*)d_in[p + 5];   // [2,10,64]
    const float* readout_w       = (const float*)d_in[p + 6];   // [2,64]
    const float* ro2_w1          = (const float*)d_in[p + 7];   // [64,16]
    const float* ro2_b1          = (const float*)d_in[p + 8];   // [16]
    const float* ro2_w2          = (const float*)d_in[p + 9];   // [16]
    const float* charge_w        = (const float*)d_in[p + 10];  // [2,64]
    const float* flux_w          = (const float*)d_in[p + 11];  // [2,8]
    const float* formal_charges  = (const float*)d_in[p + 12];  // [10]
    float* out = (float*)d_out;

    k_zero<<<(NN * FF + 255) / 256, 256>>>(out);
    k_node_init<<<NN, 64>>>(node_attrs, positions, batch,
                            atomic_energies, embed_w, formal_charges, out);
    k_edge_geom<<<(EE + 255) / 256, 256>>>(positions, edge_index, batch, flux_w, out);

    for (int l = 0; l < 2; l++) {
        k_edge_mlp<<<1024, 256>>>(radial_w1 + l * NBB * FF,
                                  radial_b1 + l * FF,
                                  radial_w2 + l * FF * FF);
        k_node_update<<<NN, 64>>>(node_attrs, batch,
                                  prod_w + l * NELS * FF,
                                  charge_w + l * FF,
                                  readout_w + l * FF,
                                  ro2_w1, ro2_b1, ro2_w2,
                                  out, (l == 1) ? 1 : 0, l + 1);
    }

    k_coulomb<<<GG * 8, 128>>>(positions, out);
    k_total_charge<<<(NN + 255) / 256, 256>>>(batch, out);
    k_finalize<<<1, 32>>>(out);
}